// round 13
// baseline (speedup 1.0000x reference)
#include <cuda_runtime.h>
#include <cuda_fp16.h>
#include <cstdint>

// Problem shapes (fixed by reference)
#define BB  2
#define HH  12
#define NN  2048
#define DD  1024
#define QKD 64
#define HNM 4096
#define MROWS (BB * NN)          // 4096
#define NBH   (BB * HH)          // 24
#define KS16  (DD / 16)          // 64 k16-steps

typedef unsigned int u32_t;

// Fragment-major fp16 buffers (uint32 = half2 units)
__device__ u32_t gA_frag[(MROWS / 16) * KS16 * 32 * 4];   // 8 MB  g  A-frags
__device__ u32_t gB_frag[(HNM / 8) * KS16 * 32 * 2];      // 8 MB  Whn B-frags
__device__ u32_t gW_frag[24 * 8 * KS16 * 32 * 2];         // 3 MB  Wq|Wk B-frags
__device__ u32_t qA_frag[NBH * 128 * 4 * 32 * 4];         // 6 MB  q  A-frags
__device__ u32_t kB_frag[NBH * 256 * 4 * 32 * 2];         // 6 MB  k  B-frags
__device__ double g_acc;

static __device__ __forceinline__ u32_t h2(float a, float b) {
    __half2 h = __floats2half2_rn(a, b);
    return *(u32_t*)&h;
}

// fp16 HMMA: D(16x8,f32) += A(16x16,f16,row) * B(16x8,f16,col)
static __device__ __forceinline__ void mma_f16(float& d0, float& d1, float& d2, float& d3,
                                               u32_t a0, u32_t a1, u32_t a2, u32_t a3,
                                               u32_t b0, u32_t b1) {
    asm volatile(
        "mma.sync.aligned.m16n8k16.row.col.f32.f16.f16.f32 "
        "{%0,%1,%2,%3}, {%4,%5,%6,%7}, {%8,%9}, {%0,%1,%2,%3};"
        : "+f"(d0), "+f"(d1), "+f"(d2), "+f"(d3)
        : "r"(a0), "r"(a1), "r"(a2), "r"(a3), "r"(b0), "r"(b1));
}

__global__ void k_init() { g_acc = 0.0; }

// ============================================================================
// Staging bodies: fp32 -> fp16(RN), fragment-major; one thread = one slot.
// ============================================================================
static __device__ __forceinline__ void stage_a_body(int t, const float* __restrict__ src) {
    int lane = t & 31;
    int ks = (t >> 5) & 63;
    int mt = t >> 11;                          // 0..255
    int r0 = mt * 16 + (lane >> 2);
    int k0 = ks * 16 + (lane & 3) * 2;
    const float* p = src + (size_t)r0 * DD + k0;
    float2 v00 = *(const float2*)p;
    float2 v10 = *(const float2*)(p + 8 * DD);
    float2 v01 = *(const float2*)(p + 8);
    float2 v11 = *(const float2*)(p + 8 * DD + 8);
    ((uint4*)gA_frag)[(size_t)t] = make_uint4(h2(v00.x, v00.y), h2(v10.x, v10.y),
                                              h2(v01.x, v01.y), h2(v11.x, v11.y));
}
static __device__ __forceinline__ void stage_w_body(int t, const float* __restrict__ Wq,
                                                    const float* __restrict__ Wk) {
    int lane = t & 31;
    int ks = (t >> 5) & 63;
    int nt = (t >> 11) & 7;
    int zh = t >> 14;                          // 0..23
    const float* src = (zh >= HH) ? Wk : Wq;
    int hh = (zh >= HH) ? (zh - HH) : zh;
    int kk = nt * 8 + (lane >> 2);
    int d0 = ks * 16 + (lane & 3) * 2;
    const float* p = src + ((size_t)hh * QKD + kk) * DD + d0;
    float2 v0 = *(const float2*)p;
    float2 v1 = *(const float2*)(p + 8);
    ((uint2*)gW_frag)[(size_t)t] = make_uint2(h2(v0.x, v0.y), h2(v1.x, v1.y));
}
static __device__ __forceinline__ void stage_b_body(int t, const float* __restrict__ src) {
    int lane = t & 31;
    int ks = (t >> 5) & 63;
    int nt = t >> 11;                          // 0..511
    int n  = nt * 8 + (lane >> 2);
    int k0 = ks * 16 + (lane & 3) * 2;
    const float* p = src + (size_t)n * DD + k0;
    float2 v0 = *(const float2*)p;
    float2 v1 = *(const float2*)(p + 8);
    ((uint2*)gB_frag)[(size_t)t] = make_uint2(h2(v0.x, v0.y), h2(v1.x, v1.y));
}

// stage_a (2048 blocks) + stage_w (1536 blocks) in one launch
__global__ __launch_bounds__(256) void k_stage_aw(const float* __restrict__ g,
                                                  const float* __restrict__ Wq,
                                                  const float* __restrict__ Wk) {
    int bid = blockIdx.x;
    if (bid < 2048) stage_a_body(bid * 256 + threadIdx.x, g);
    else            stage_w_body((bid - 2048) * 256 + threadIdx.x, Wq, Wk);
}

// ============================================================================
// Projection body: QK projection via fp16 MMA; q -> A-frags, k -> B-frags.
// ============================================================================
static __device__ __forceinline__ void proj_body(int bid) {
    const int t    = threadIdx.x;
    const int lane = t & 31;
    const int wid  = t >> 5;
    const int wm   = wid & 3;          // 0..3
    const int wn   = wid >> 2;         // 0..1
    const int h    = bid % 12;
    const int R    = (bid / 12) % 32;
    const int z    = bid / (12 * 32);

    float acc[2][4][4];
#pragma unroll
    for (int i = 0; i < 2; ++i)
#pragma unroll
        for (int j = 0; j < 4; ++j)
#pragma unroll
            for (int c = 0; c < 4; ++c) acc[i][j][c] = 0.0f;

    const uint4* Ab = ((const uint4*)gA_frag) + lane;
    const uint2* Bb = ((const uint2*)gW_frag) + lane;
    size_t aOff[2], bOff[4];
#pragma unroll
    for (int i = 0; i < 2; ++i) aOff[i] = ((size_t)(R * 8 + wm * 2 + i) * KS16) * 32;
#pragma unroll
    for (int j = 0; j < 4; ++j)
        bOff[j] = (((size_t)(z * HH + h) * 8 + (wn * 4 + j)) * KS16) * 32;

#pragma unroll 2
    for (int ks = 0; ks < KS16; ++ks) {
        uint4 a[2]; uint2 b[4];
#pragma unroll
        for (int i = 0; i < 2; ++i) a[i] = Ab[aOff[i] + (size_t)ks * 32];
#pragma unroll
        for (int j = 0; j < 4; ++j) b[j] = Bb[bOff[j] + (size_t)ks * 32];
#pragma unroll
        for (int i = 0; i < 2; ++i)
#pragma unroll
            for (int j = 0; j < 4; ++j)
                mma_f16(acc[i][j][0], acc[i][j][1], acc[i][j][2], acc[i][j][3],
                        a[i].x, a[i].y, a[i].z, a[i].w, b[j].x, b[j].y);
    }

    // Epilogue: D lane mapping == fp16 fragment lane mapping (lane'==lane).
#pragma unroll
    for (int i = 0; i < 2; ++i) {
        int mtg = R * 8 + wm * 2 + i;          // 0..255
        int bb  = mtg >> 7;
        int bh  = bb * HH + h;
#pragma unroll
        for (int j = 0; j < 4; ++j) {
            int ks = (wn * 4 + j) >> 1;
            if (z == 0) {
                int mt = mtg & 127;
                u32_t* base = qA_frag +
                    ((((size_t)bh * 128 + mt) * 4 + ks) * 32 + lane) * 4;
                base[2 * (j & 1)]     = h2(acc[i][j][0], acc[i][j][1]);
                base[2 * (j & 1) + 1] = h2(acc[i][j][2], acc[i][j][3]);
            } else {
                int nt0 = (mtg & 127) * 2;
                u32_t* b0 = kB_frag +
                    ((((size_t)bh * 256 + nt0) * 4 + ks) * 32 + lane) * 2;
                u32_t* b1 = kB_frag +
                    ((((size_t)bh * 256 + nt0 + 1) * 4 + ks) * 32 + lane) * 2;
                b0[j & 1] = h2(acc[i][j][0], acc[i][j][1]);
                b1[j & 1] = h2(acc[i][j][2], acc[i][j][3]);
            }
        }
    }
}

// proj (768 blocks) + stage_b (4096 blocks) in one launch
__global__ __launch_bounds__(256) void k_proj_sb(const float* __restrict__ Whn) {
    int bid = blockIdx.x;
    if (bid < 768) proj_body(bid);
    else           stage_b_body((bid - 768) * 256 + threadIdx.x, Whn);
}

// ============================================================================
// Fused main kernel: Hopfield (2048 CTAs, 64x128 CTA tiles, warp 32x32) +
// attention (384 CTAs). __launch_bounds__(256,4) -> <=64 regs -> 4 CTAs/SM.
// ============================================================================
#define HOP_BLOCKS  2048
#define ATTN_BLOCKS (16 * NBH)    // 384

static __device__ __forceinline__ void hop_body(int hb) {
    const int t    = threadIdx.x;
    const int lane = t & 31;
    const int wid  = t >> 5;
    const int wm   = wid >> 2;         // 0..1  (M: 32 rows each)
    const int wn   = wid & 3;          // 0..3  (N: 32 cols each)
    const int col  = hb & 31;          // 128-wide col tile
    const int row  = hb >> 5;          // 64-tall row tile (0..63)

    float acc[2][4][4];
#pragma unroll
    for (int i = 0; i < 2; ++i)
#pragma unroll
        for (int j = 0; j < 4; ++j)
#pragma unroll
            for (int c = 0; c < 4; ++c) acc[i][j][c] = 0.0f;

    const uint4* Ap = ((const uint4*)gA_frag) +
        ((size_t)(row * 4 + wm * 2) * KS16) * 32 + lane;
    const uint2* Bp = ((const uint2*)gB_frag) +
        ((size_t)(col * 16 + wn * 4) * KS16) * 32 + lane;

#pragma unroll 2
    for (int ks = 0; ks < KS16; ++ks) {
        uint4 a[2]; uint2 b[4];
#pragma unroll
        for (int i = 0; i < 2; ++i) a[i] = Ap[(size_t)i * (KS16 * 32) + ks * 32];
#pragma unroll
        for (int j = 0; j < 4; ++j) b[j] = Bp[(size_t)j * (KS16 * 32) + ks * 32];
#pragma unroll
        for (int i = 0; i < 2; ++i)
#pragma unroll
            for (int j = 0; j < 4; ++j)
                mma_f16(acc[i][j][0], acc[i][j][1], acc[i][j][2], acc[i][j][3],
                        a[i].x, a[i].y, a[i].z, a[i].w, b[j].x, b[j].y);
    }

    float local = 0.0f;
#pragma unroll
    for (int i = 0; i < 2; ++i)
#pragma unroll
        for (int j = 0; j < 4; ++j)
#pragma unroll
            for (int c = 0; c < 4; ++c) {
                float v = fmaxf(acc[i][j][c], 0.0f);
                local += v * v;
            }

    __shared__ float red[256];
    red[t] = local;
    __syncthreads();
    for (int s = 128; s > 0; s >>= 1) {
        if (t < s) red[t] += red[t + s];
        __syncthreads();
    }
    if (t == 0) atomicAdd(&g_acc, -0.5 * (double)red[0]);
}

static __device__ __forceinline__ void attn_body(int bid) {
    const int t    = threadIdx.x;
    const int lane = t & 31;
    const int wid  = t >> 5;
    const int bh   = bid >> 4;
    const int mt   = (bid & 15) * 8 + wid;     // 0..127

    const uint4* Aq = ((const uint4*)qA_frag) + ((size_t)(bh * 128 + mt) * 4) * 32 + lane;
    uint4 aq[4];
#pragma unroll
    for (int ks = 0; ks < 4; ++ks) aq[ks] = Aq[(size_t)ks * 32];

    const uint2* Kb = ((const uint2*)kB_frag) + ((size_t)bh * 256 * 4) * 32 + lane;

    const float LB = 0.125f * 1.4426950408889634f;   // beta * log2(e)
    float lsum0 = 0.0f, lsum8 = 0.0f;

#pragma unroll 4
    for (int nt = 0; nt < 256; ++nt) {
        uint2 kk0 = Kb[(size_t)(nt * 4 + 0) * 32];
        uint2 kk1 = Kb[(size_t)(nt * 4 + 1) * 32];
        uint2 kk2 = Kb[(size_t)(nt * 4 + 2) * 32];
        uint2 kk3 = Kb[(size_t)(nt * 4 + 3) * 32];
        float d0 = 0.f, d1 = 0.f, d2 = 0.f, d3 = 0.f;
        mma_f16(d0, d1, d2, d3, aq[0].x, aq[0].y, aq[0].z, aq[0].w, kk0.x, kk0.y);
        mma_f16(d0, d1, d2, d3, aq[1].x, aq[1].y, aq[1].z, aq[1].w, kk1.x, kk1.y);
        mma_f16(d0, d1, d2, d3, aq[2].x, aq[2].y, aq[2].z, aq[2].w, kk2.x, kk2.y);
        mma_f16(d0, d1, d2, d3, aq[3].x, aq[3].y, aq[3].z, aq[3].w, kk3.x, kk3.y);
        lsum0 += exp2f(d0 * LB) + exp2f(d1 * LB);
        lsum8 += exp2f(d2 * LB) + exp2f(d3 * LB);
    }

    lsum0 += __shfl_xor_sync(0xFFFFFFFFu, lsum0, 1);
    lsum0 += __shfl_xor_sync(0xFFFFFFFFu, lsum0, 2);
    lsum8 += __shfl_xor_sync(0xFFFFFFFFu, lsum8, 1);
    lsum8 += __shfl_xor_sync(0xFFFFFFFFu, lsum8, 2);

    float v = __log2f(lsum0) + __log2f(lsum8);
    v += __shfl_xor_sync(0xFFFFFFFFu, v, 4);
    v += __shfl_xor_sync(0xFFFFFFFFu, v, 8);
    v += __shfl_xor_sync(0xFFFFFFFFu, v, 16);

    __shared__ float red8[8];
    if (lane == 0) red8[wid] = v;
    __syncthreads();
    if (t == 0) {
        float s = 0.f;
#pragma unroll
        for (int i = 0; i < 8; ++i) s += red8[i];
        atomicAdd(&g_acc, -8.0 * 0.6931471805599453 * (double)s);
    }
}

__global__ __launch_bounds__(256, 4) void k_fused() {
    if (blockIdx.x < HOP_BLOCKS) hop_body(blockIdx.x);
    else                         attn_body(blockIdx.x - HOP_BLOCKS);
}

__global__ void k_fin(float* out) { out[0] = (float)g_acc; }

// ============================================================================
extern "C" void kernel_launch(void* const* d_in, const int* in_sizes, int n_in,
                              void* d_out, int out_size) {
    const float* g   = (const float*)d_in[0];  // [2,2048,1024]
    const float* Wq  = (const float*)d_in[1];  // [12,64,1024]
    const float* Wk  = (const float*)d_in[2];  // [12,64,1024]
    const float* Whn = (const float*)d_in[3];  // [4096,1024]

    k_init<<<1, 1>>>();
    k_stage_aw<<<2048 + 1536, 256>>>(g, Wq, Wk);
    k_proj_sb<<<768 + 4096, 256>>>(Whn);
    k_fused<<<HOP_BLOCKS + ATTN_BLOCKS, 256>>>();
    k_fin<<<1, 1>>>((float*)d_out);
}

// round 14
// speedup vs baseline: 1.1283x; 1.1283x over previous
#include <cuda_runtime.h>
#include <cuda_fp16.h>
#include <cstdint>

// Problem shapes (fixed by reference)
#define BB  2
#define HH  12
#define NN  2048
#define DD  1024
#define QKD 64
#define HNM 4096
#define MROWS (BB * NN)          // 4096
#define NBH   (BB * HH)          // 24
#define KS16  (DD / 16)          // 64 k16-steps

typedef unsigned int u32_t;

// Fragment-major fp16 buffers (uint32 = half2 units)
__device__ u32_t gA_frag[(MROWS / 16) * KS16 * 32 * 4];   // 8 MB  g  A-frags
__device__ u32_t gB_frag[(HNM / 8) * KS16 * 32 * 2];      // 8 MB  Whn B-frags
__device__ u32_t gW_frag[24 * 8 * KS16 * 32 * 2];         // 3 MB  Wq|Wk B-frags
__device__ u32_t qA_frag[NBH * 128 * 4 * 32 * 4];         // 6 MB  q  A-frags
__device__ u32_t kB_frag[NBH * 256 * 4 * 32 * 2];         // 6 MB  k  B-frags
__device__ double g_acc;

static __device__ __forceinline__ u32_t h2(float a, float b) {
    __half2 h = __floats2half2_rn(a, b);
    return *(u32_t*)&h;
}

// fp16 HMMA: D(16x8,f32) += A(16x16,f16,row) * B(16x8,f16,col)
static __device__ __forceinline__ void mma_f16(float& d0, float& d1, float& d2, float& d3,
                                               u32_t a0, u32_t a1, u32_t a2, u32_t a3,
                                               u32_t b0, u32_t b1) {
    asm volatile(
        "mma.sync.aligned.m16n8k16.row.col.f32.f16.f16.f32 "
        "{%0,%1,%2,%3}, {%4,%5,%6,%7}, {%8,%9}, {%0,%1,%2,%3};"
        : "+f"(d0), "+f"(d1), "+f"(d2), "+f"(d3)
        : "r"(a0), "r"(a1), "r"(a2), "r"(a3), "r"(b0), "r"(b1));
}

// ============================================================================
// Staging bodies: fp32 -> fp16(RN), fragment-major; one thread = one slot.
// ============================================================================
static __device__ __forceinline__ void stage_a_body(int t, const float* __restrict__ src) {
    int lane = t & 31;
    int ks = (t >> 5) & 63;
    int mt = t >> 11;                          // 0..255
    int r0 = mt * 16 + (lane >> 2);
    int k0 = ks * 16 + (lane & 3) * 2;
    const float* p = src + (size_t)r0 * DD + k0;
    float2 v00 = *(const float2*)p;
    float2 v10 = *(const float2*)(p + 8 * DD);
    float2 v01 = *(const float2*)(p + 8);
    float2 v11 = *(const float2*)(p + 8 * DD + 8);
    ((uint4*)gA_frag)[(size_t)t] = make_uint4(h2(v00.x, v00.y), h2(v10.x, v10.y),
                                              h2(v01.x, v01.y), h2(v11.x, v11.y));
}
static __device__ __forceinline__ void stage_w_body(int t, const float* __restrict__ Wq,
                                                    const float* __restrict__ Wk) {
    int lane = t & 31;
    int ks = (t >> 5) & 63;
    int nt = (t >> 11) & 7;
    int zh = t >> 14;                          // 0..23
    const float* src = (zh >= HH) ? Wk : Wq;
    int hh = (zh >= HH) ? (zh - HH) : zh;
    int kk = nt * 8 + (lane >> 2);
    int d0 = ks * 16 + (lane & 3) * 2;
    const float* p = src + ((size_t)hh * QKD + kk) * DD + d0;
    float2 v0 = *(const float2*)p;
    float2 v1 = *(const float2*)(p + 8);
    ((uint2*)gW_frag)[(size_t)t] = make_uint2(h2(v0.x, v0.y), h2(v1.x, v1.y));
}
static __device__ __forceinline__ void stage_b_body(int t, const float* __restrict__ src) {
    int lane = t & 31;
    int ks = (t >> 5) & 63;
    int nt = t >> 11;                          // 0..511
    int n  = nt * 8 + (lane >> 2);
    int k0 = ks * 16 + (lane & 3) * 2;
    const float* p = src + (size_t)n * DD + k0;
    float2 v0 = *(const float2*)p;
    float2 v1 = *(const float2*)(p + 8);
    ((uint2*)gB_frag)[(size_t)t] = make_uint2(h2(v0.x, v0.y), h2(v1.x, v1.y));
}

// stage_a (2048 blocks) + stage_w (1536 blocks) in one launch.
// Block 0 also zeroes the energy accumulator (stream-ordered before k_fused).
__global__ __launch_bounds__(256) void k_stage_aw(const float* __restrict__ g,
                                                  const float* __restrict__ Wq,
                                                  const float* __restrict__ Wk) {
    int bid = blockIdx.x;
    if (bid == 0 && threadIdx.x == 0) g_acc = 0.0;
    if (bid < 2048) stage_a_body(bid * 256 + threadIdx.x, g);
    else            stage_w_body((bid - 2048) * 256 + threadIdx.x, Wq, Wk);
}

// ============================================================================
// Projection body: QK projection via fp16 MMA; q -> A-frags, k -> B-frags.
// ============================================================================
static __device__ __forceinline__ void proj_body(int bid) {
    const int t    = threadIdx.x;
    const int lane = t & 31;
    const int wid  = t >> 5;
    const int wm   = wid & 3;          // 0..3
    const int wn   = wid >> 2;         // 0..1
    const int h    = bid % 12;
    const int R    = (bid / 12) % 32;
    const int z    = bid / (12 * 32);

    float acc[2][4][4];
#pragma unroll
    for (int i = 0; i < 2; ++i)
#pragma unroll
        for (int j = 0; j < 4; ++j)
#pragma unroll
            for (int c = 0; c < 4; ++c) acc[i][j][c] = 0.0f;

    const uint4* Ab = ((const uint4*)gA_frag) + lane;
    const uint2* Bb = ((const uint2*)gW_frag) + lane;
    size_t aOff[2], bOff[4];
#pragma unroll
    for (int i = 0; i < 2; ++i) aOff[i] = ((size_t)(R * 8 + wm * 2 + i) * KS16) * 32;
#pragma unroll
    for (int j = 0; j < 4; ++j)
        bOff[j] = (((size_t)(z * HH + h) * 8 + (wn * 4 + j)) * KS16) * 32;

#pragma unroll 2
    for (int ks = 0; ks < KS16; ++ks) {
        uint4 a[2]; uint2 b[4];
#pragma unroll
        for (int i = 0; i < 2; ++i) a[i] = Ab[aOff[i] + (size_t)ks * 32];
#pragma unroll
        for (int j = 0; j < 4; ++j) b[j] = Bb[bOff[j] + (size_t)ks * 32];
#pragma unroll
        for (int i = 0; i < 2; ++i)
#pragma unroll
            for (int j = 0; j < 4; ++j)
                mma_f16(acc[i][j][0], acc[i][j][1], acc[i][j][2], acc[i][j][3],
                        a[i].x, a[i].y, a[i].z, a[i].w, b[j].x, b[j].y);
    }

    // Epilogue: D lane mapping == fp16 fragment lane mapping (lane'==lane).
#pragma unroll
    for (int i = 0; i < 2; ++i) {
        int mtg = R * 8 + wm * 2 + i;          // 0..255
        int bb  = mtg >> 7;
        int bh  = bb * HH + h;
#pragma unroll
        for (int j = 0; j < 4; ++j) {
            int ks = (wn * 4 + j) >> 1;
            if (z == 0) {
                int mt = mtg & 127;
                u32_t* base = qA_frag +
                    ((((size_t)bh * 128 + mt) * 4 + ks) * 32 + lane) * 4;
                base[2 * (j & 1)]     = h2(acc[i][j][0], acc[i][j][1]);
                base[2 * (j & 1) + 1] = h2(acc[i][j][2], acc[i][j][3]);
            } else {
                int nt0 = (mtg & 127) * 2;
                u32_t* b0 = kB_frag +
                    ((((size_t)bh * 256 + nt0) * 4 + ks) * 32 + lane) * 2;
                u32_t* b1 = kB_frag +
                    ((((size_t)bh * 256 + nt0 + 1) * 4 + ks) * 32 + lane) * 2;
                b0[j & 1] = h2(acc[i][j][0], acc[i][j][1]);
                b1[j & 1] = h2(acc[i][j][2], acc[i][j][3]);
            }
        }
    }
}

// proj (768 blocks) + stage_b (4096 blocks) in one launch
__global__ __launch_bounds__(256) void k_proj_sb(const float* __restrict__ Whn) {
    int bid = blockIdx.x;
    if (bid < 768) proj_body(bid);
    else           stage_b_body((bid - 768) * 256 + threadIdx.x, Whn);
}

// ============================================================================
// Fused main kernel. LPT order: attention CTAs (long) FIRST, then Hopfield
// (2048 CTAs, 64x128 tiles, warp 32x32). (256,3) -> 72 regs, 3 CTAs/SM —
// the empirically optimal occupancy/register balance (round 12).
// ============================================================================
#define HOP_BLOCKS  2048
#define ATTN_BLOCKS (16 * NBH)    // 384

static __device__ __forceinline__ void hop_body(int hb) {
    const int t    = threadIdx.x;
    const int lane = t & 31;
    const int wid  = t >> 5;
    const int wm   = wid >> 2;         // 0..1  (M: 32 rows each)
    const int wn   = wid & 3;          // 0..3  (N: 32 cols each)
    const int col  = hb & 31;          // 128-wide col tile
    const int row  = hb >> 5;          // 64-tall row tile (0..63)

    float acc[2][4][4];
#pragma unroll
    for (int i = 0; i < 2; ++i)
#pragma unroll
        for (int j = 0; j < 4; ++j)
#pragma unroll
            for (int c = 0; c < 4; ++c) acc[i][j][c] = 0.0f;

    const uint4* Ap = ((const uint4*)gA_frag) +
        ((size_t)(row * 4 + wm * 2) * KS16) * 32 + lane;
    const uint2* Bp = ((const uint2*)gB_frag) +
        ((size_t)(col * 16 + wn * 4) * KS16) * 32 + lane;

#pragma unroll 2
    for (int ks = 0; ks < KS16; ++ks) {
        uint4 a[2]; uint2 b[4];
#pragma unroll
        for (int i = 0; i < 2; ++i) a[i] = Ap[(size_t)i * (KS16 * 32) + ks * 32];
#pragma unroll
        for (int j = 0; j < 4; ++j) b[j] = Bp[(size_t)j * (KS16 * 32) + ks * 32];
#pragma unroll
        for (int i = 0; i < 2; ++i)
#pragma unroll
            for (int j = 0; j < 4; ++j)
                mma_f16(acc[i][j][0], acc[i][j][1], acc[i][j][2], acc[i][j][3],
                        a[i].x, a[i].y, a[i].z, a[i].w, b[j].x, b[j].y);
    }

    float local = 0.0f;
#pragma unroll
    for (int i = 0; i < 2; ++i)
#pragma unroll
        for (int j = 0; j < 4; ++j)
#pragma unroll
            for (int c = 0; c < 4; ++c) {
                float v = fmaxf(acc[i][j][c], 0.0f);
                local += v * v;
            }

    __shared__ float red[256];
    red[t] = local;
    __syncthreads();
    for (int s = 128; s > 0; s >>= 1) {
        if (t < s) red[t] += red[t + s];
        __syncthreads();
    }
    if (t == 0) atomicAdd(&g_acc, -0.5 * (double)red[0]);
}

static __device__ __forceinline__ void attn_body(int bid) {
    const int t    = threadIdx.x;
    const int lane = t & 31;
    const int wid  = t >> 5;
    const int bh   = bid >> 4;
    const int mt   = (bid & 15) * 8 + wid;     // 0..127

    const uint4* Aq = ((const uint4*)qA_frag) + ((size_t)(bh * 128 + mt) * 4) * 32 + lane;
    uint4 aq[4];
#pragma unroll
    for (int ks = 0; ks < 4; ++ks) aq[ks] = Aq[(size_t)ks * 32];

    const uint2* Kb = ((const uint2*)kB_frag) + ((size_t)bh * 256 * 4) * 32 + lane;

    const float LB = 0.125f * 1.4426950408889634f;   // beta * log2(e)
    float lsum0 = 0.0f, lsum8 = 0.0f;

#pragma unroll 4
    for (int nt = 0; nt < 256; ++nt) {
        uint2 kk0 = Kb[(size_t)(nt * 4 + 0) * 32];
        uint2 kk1 = Kb[(size_t)(nt * 4 + 1) * 32];
        uint2 kk2 = Kb[(size_t)(nt * 4 + 2) * 32];
        uint2 kk3 = Kb[(size_t)(nt * 4 + 3) * 32];
        float d0 = 0.f, d1 = 0.f, d2 = 0.f, d3 = 0.f;
        mma_f16(d0, d1, d2, d3, aq[0].x, aq[0].y, aq[0].z, aq[0].w, kk0.x, kk0.y);
        mma_f16(d0, d1, d2, d3, aq[1].x, aq[1].y, aq[1].z, aq[1].w, kk1.x, kk1.y);
        mma_f16(d0, d1, d2, d3, aq[2].x, aq[2].y, aq[2].z, aq[2].w, kk2.x, kk2.y);
        mma_f16(d0, d1, d2, d3, aq[3].x, aq[3].y, aq[3].z, aq[3].w, kk3.x, kk3.y);
        lsum0 += exp2f(d0 * LB) + exp2f(d1 * LB);
        lsum8 += exp2f(d2 * LB) + exp2f(d3 * LB);
    }

    lsum0 += __shfl_xor_sync(0xFFFFFFFFu, lsum0, 1);
    lsum0 += __shfl_xor_sync(0xFFFFFFFFu, lsum0, 2);
    lsum8 += __shfl_xor_sync(0xFFFFFFFFu, lsum8, 1);
    lsum8 += __shfl_xor_sync(0xFFFFFFFFu, lsum8, 2);

    float v = __log2f(lsum0) + __log2f(lsum8);
    v += __shfl_xor_sync(0xFFFFFFFFu, v, 4);
    v += __shfl_xor_sync(0xFFFFFFFFu, v, 8);
    v += __shfl_xor_sync(0xFFFFFFFFu, v, 16);

    __shared__ float red8[8];
    if (lane == 0) red8[wid] = v;
    __syncthreads();
    if (t == 0) {
        float s = 0.f;
#pragma unroll
        for (int i = 0; i < 8; ++i) s += red8[i];
        atomicAdd(&g_acc, -8.0 * 0.6931471805599453 * (double)s);
    }
}

__global__ __launch_bounds__(256, 3) void k_fused() {
    if (blockIdx.x < ATTN_BLOCKS) attn_body(blockIdx.x);
    else                          hop_body(blockIdx.x - ATTN_BLOCKS);
}

__global__ void k_fin(float* out) { out[0] = (float)g_acc; }

// ============================================================================
extern "C" void kernel_launch(void* const* d_in, const int* in_sizes, int n_in,
                              void* d_out, int out_size) {
    const float* g   = (const float*)d_in[0];  // [2,2048,1024]
    const float* Wq  = (const float*)d_in[1];  // [12,64,1024]
    const float* Wk  = (const float*)d_in[2];  // [12,64,1024]
    const float* Whn = (const float*)d_in[3];  // [4096,1024]

    k_stage_aw<<<2048 + 1536, 256>>>(g, Wq, Wk);
    k_proj_sb<<<768 + 4096, 256>>>(Whn);
    k_fused<<<ATTN_BLOCKS + HOP_BLOCKS, 256>>>();
    k_fin<<<1, 1>>>((float*)d_out);
}